// round 16
// baseline (speedup 1.0000x reference)
#include <cuda_runtime.h>
#include <cuda_bf16.h>
#include <cstdint>
#include <math.h>

#define EMBED   256
#define NHEADS  8
#define HDIM    32
#define NPAIRS  16
#define NLEV    4
#define FULL    128
#define KPQ     164
#define MAXQ    2048
#define MAXB    2
#define NCELLS  (MAXB * NLEV * FULL * FULL)
#define MAXROWS 43520
#define GP      40
#define QR      4

// Scratch (device globals; no runtime allocation allowed). 16B-aligned so
// float4/uint4 accesses are safe.
__device__ __align__(16) float g_Kmap[NCELLS * EMBED];
__device__ __align__(16) float g_Vmap[NCELLS * EMBED];
__device__ __align__(16) float g_qrot[MAXQ * EMBED];
__device__ __align__(16) float g_tmp [MAXQ * EMBED];
__device__ int   g_mask[NCELLS];
__device__ int   g_rows[NCELLS];
__device__ int   g_nactive;
__device__ int   g_rowOff[MAXQ * KPQ];
__device__ float g_ksp0[MAXQ * KPQ];
__device__ float g_ksp1[MAXQ * KPQ];
__device__ __align__(16) __nv_bfloat16 g_Ah[MAXROWS * EMBED];
__device__ __align__(16) __nv_bfloat16 g_Al[MAXROWS * EMBED];
__device__ __align__(16) __nv_bfloat16 g_WTh[2 * EMBED * EMBED];
__device__ __align__(16) __nv_bfloat16 g_WTl[2 * EMBED * EMBED];

// ---------------------------------------------------------------------------
// mma helpers
// ---------------------------------------------------------------------------
__device__ __forceinline__ unsigned smem_u32(const void* p)
{
    return (unsigned)__cvta_generic_to_shared(p);
}

__device__ __forceinline__ void ldm4(unsigned* r, unsigned a)
{
    asm volatile("ldmatrix.sync.aligned.m8n8.x4.shared.b16 {%0,%1,%2,%3}, [%4];"
        : "=r"(r[0]), "=r"(r[1]), "=r"(r[2]), "=r"(r[3]) : "r"(a));
}

__device__ __forceinline__ void mma16816(float* d, const unsigned* a, const unsigned* b)
{
    asm volatile("mma.sync.aligned.m16n8k16.row.col.f32.bf16.bf16.f32 "
        "{%0,%1,%2,%3}, {%4,%5,%6,%7}, {%8,%9}, {%0,%1,%2,%3};"
        : "+f"(d[0]), "+f"(d[1]), "+f"(d[2]), "+f"(d[3])
        : "r"(a[0]), "r"(a[1]), "r"(a[2]), "r"(a[3]), "r"(b[0]), "r"(b[1]));
}

// ---------------------------------------------------------------------------
__global__ void zero_kernel()
{
    int i = blockIdx.x * blockDim.x + threadIdx.x;
    if (i < NCELLS) { g_mask[i] = 0; }
    if (i == 0) { g_nactive = 0; }
}

// ---------------------------------------------------------------------------
__global__ void prep_kernel(const float* __restrict__ qpos,
                            const int* __restrict__ boff, int n_off,
                            const int* __restrict__ shp, int n_q)
{
    int n = blockIdx.x, t = threadIdx.x;
    if (n >= n_q || t >= KPQ) { return; }
    int l, base;
    if      (t < 9)  { l = 0; base = 0;  }
    else if (t < 34) { l = 1; base = 9;  }
    else if (t < 83) { l = 2; base = 34; }
    else             { l = 3; base = 83; }
    int s = 2 * l + 3, half = l + 1, j = t - base;
    int o0 = j / s - half, o1 = j % s - half;
    int H = shp[2 * l], W = shp[2 * l + 1];
    int maxH = 0, maxW = 0;
    for (int li = 0; li < NLEV; li++) {
        maxH = max(maxH, shp[2 * li]);
        maxW = max(maxW, shp[2 * li + 1]);
    }
    float p0 = qpos[n * 2 + 0], p1 = qpos[n * 2 + 1];
    int c0 = (int)floorf(p0 * ((float)H / (float)maxH));
    int c1 = (int)floorf(p1 * ((float)W / (float)maxW));
    int i0 = c0 + o0, i1 = c1 + o1;
    bool valid = (i0 >= 0) && (i0 < H) && (i1 >= 0) && (i1 < W);
    int b = 0;
    for (int ii = 1; ii < n_off - 1; ii++) {
        if (n >= boff[ii]) { b = ii; }
    }
    int cell = ((b * NLEV + l) * FULL + i0) * FULL + i1;
    g_rowOff[n * KPQ + t] = valid ? cell * EMBED : -1;
    if (valid) { g_mask[cell] = 1; }
    g_ksp0[n * KPQ + t] = (i0 + 0.5f) * ((float)maxH / (float)H);
    g_ksp1[n * KPQ + t] = (i1 + 0.5f) * ((float)maxW / (float)W);
}

// ---------------------------------------------------------------------------
__global__ void compact_kernel()
{
    int i = blockIdx.x * blockDim.x + threadIdx.x;
    if (i < NCELLS && g_mask[i]) {
        int p = atomicAdd(&g_nactive, 1);
        g_rows[p] = i;
    }
}

// ---------------------------------------------------------------------------
__global__ void convert_w_kernel(const float* __restrict__ kw,
                                 const float* __restrict__ vw)
{
    int idx = blockIdx.x * blockDim.x + threadIdx.x;
    if (idx >= 2 * EMBED * EMBED) { return; }
    int w = idx >> 16;
    int rem = idx & 0xFFFF;
    int k = rem >> 8;
    int n = rem & 255;
    float x = (w ? vw : kw)[k * EMBED + n];
    __nv_bfloat16 h = __float2bfloat16(x);
    __nv_bfloat16 lo = __float2bfloat16(x - __bfloat162float(h));
    g_WTh[(w << 16) + n * EMBED + k] = h;
    g_WTl[(w << 16) + n * EMBED + k] = lo;
}

// ---------------------------------------------------------------------------
__global__ __launch_bounds__(256) void convert_a_kernel(const float* __restrict__ fm)
{
    const int nact = g_nactive;
    int e4 = blockIdx.x * blockDim.x + threadIdx.x;
    int r = e4 >> 6;
    if (r >= nact) { return; }
    int c = (e4 & 63) * 4;
    const float4 v = *(const float4*)(fm + g_rows[r] * EMBED + c);
    float xs[4];
    xs[0] = v.x; xs[1] = v.y; xs[2] = v.z; xs[3] = v.w;
    __nv_bfloat16 hh[4];
    __nv_bfloat16 ll[4];
    for (int j = 0; j < 4; j++) {
        hh[j] = __float2bfloat16(xs[j]);
        ll[j] = __float2bfloat16(xs[j] - __bfloat162float(hh[j]));
    }
    *(uint2*)(g_Ah + r * EMBED + c) = *(uint2*)hh;
    *(uint2*)(g_Al + r * EMBED + c) = *(uint2*)ll;
}

// ---------------------------------------------------------------------------
// Kernel 1: LayerNorm + Q projection + RoPE.  4 queries per block.
// ---------------------------------------------------------------------------
__global__ __launch_bounds__(256) void qln_kernel(
    const float* __restrict__ query, const float* __restrict__ qpos,
    const float* __restrict__ nw, const float* __restrict__ nb,
    const float* __restrict__ qw, const float* __restrict__ rf, int n_q)
{
    const int t  = threadIdx.x;
    const int n0 = blockIdx.x * QR;
    __shared__ float xs[QR][EMBED];
    __shared__ float red[16];

    float val[QR];
    for (int r = 0; r < QR; r++) {
        int n = n0 + r;
        val[r] = (n < n_q) ? query[n * EMBED + t] : 0.f;
    }
    for (int r = 0; r < QR; r++) {
        float s = val[r], s2 = val[r] * val[r];
        for (int o = 16; o; o >>= 1) {
            s  += __shfl_xor_sync(~0u, s, o);
            s2 += __shfl_xor_sync(~0u, s2, o);
        }
        int w = t >> 5;
        if ((t & 31) == 0) { red[w] = s; red[8 + w] = s2; }
        __syncthreads();
        float sum = 0.f, sum2 = 0.f;
        for (int i = 0; i < 8; i++) { sum += red[i]; sum2 += red[8 + i]; }
        __syncthreads();
        float mean = sum * (1.0f / EMBED);
        float var  = sum2 * (1.0f / EMBED) - mean * mean;
        float inv  = rsqrtf(var + 1e-5f);
        xs[r][t] = (val[r] - mean) * inv * nw[t] + nb[t];
    }
    __syncthreads();

    float acc[QR];
    for (int r = 0; r < QR; r++) { acc[r] = 0.f; }
    #pragma unroll 8
    for (int i = 0; i < EMBED; i++) {
        float w = qw[i * EMBED + t];
        for (int r = 0; r < QR; r++) { acc[r] += xs[r][i] * w; }
    }
    __syncthreads();
    for (int r = 0; r < QR; r++) { xs[r][t] = acc[r]; }
    __syncthreads();

    const int p = (t & 31) >> 1;
    const float f0 = rf[p], f1 = rf[NPAIRS + p];
    for (int r = 0; r < QR; r++) {
        int n = n0 + r;
        if (n >= n_q) { break; }
        float ang = qpos[n * 2 + 0] * f0 + qpos[n * 2 + 1] * f1;
        float sn, cs;
        __sincosf(ang, &sn, &cs);
        float x1 = xs[r][t & ~1], x2 = xs[r][t | 1];
        g_qrot[n * EMBED + t] = ((t & 1) == 0) ? (x1 * cs - x2 * sn)
                                               : (x1 * sn + x2 * cs);
    }
}

// ---------------------------------------------------------------------------
// Kernel 2: tensor-core K/V GEMM over compacted rows (split bf16, 3 terms).
// Register-staged double buffering. NOTE: g_Ah/g_Al are indexed by COMPACT
// row index (row0 + r), NOT by cell id — cell ids only appear in sRow for
// the epilogue scatter into g_Kmap/g_Vmap.
// Block: 64 rows x 128 cols. 8 warps as 2(m) x 4(n), warp tile 32x32.
// grid.x: bit1 = K/V weight, bit0 = col half. grid.y: row tiles.
// ---------------------------------------------------------------------------
__global__ __launch_bounds__(256) void kv_gemm_mma()
{
    const int nact = g_nactive;
    const int row0 = blockIdx.y * 64;
    if (row0 >= nact) { return; }

    const int bx   = blockIdx.x;
    const int wsel = (bx >> 1) & 1;
    float* outp    = wsel ? g_Vmap : g_Kmap;
    const int col0 = (bx & 1) * 128;

    __shared__ __nv_bfloat16 sAh[64 * GP];
    __shared__ __nv_bfloat16 sAl[64 * GP];
    __shared__ __nv_bfloat16 sBh[128 * GP];
    __shared__ __nv_bfloat16 sBl[128 * GP];
    __shared__ int sRow[64];

    const int tid = threadIdx.x;
    if (tid < 64) {
        int r = row0 + tid;
        sRow[tid] = (r < nact) ? g_rows[r] * EMBED : -1;
    }

    // ---- load-thread mappings (COMPACT row indexing, clamped in-bounds) ----
    const int rA0 = tid >> 3;            // rows 0..31
    const int rA1 = rA0 + 32;            // rows 32..63
    const int cA  = (tid & 7) * 4;
    const long aOff0 = (long)min(row0 + rA0, nact - 1) * EMBED + cA;
    const long aOff1 = (long)min(row0 + rA1, nact - 1) * EMBED + cA;

    const int nB0 = tid >> 2;            // 0..63
    const int nB1 = nB0 + 64;            // 64..127
    const int k8  = (tid & 3) * 8;
    const __nv_bfloat16* WTh = g_WTh + (wsel << 16);
    const __nv_bfloat16* WTl = g_WTl + (wsel << 16);
    const long bOff0 = (long)(col0 + nB0) * EMBED + k8;
    const long bOff1 = (long)(col0 + nB1) * EMBED + k8;

    // staging registers
    uint2 avh0, avl0, avh1, avl1;
    uint4 bvh0, bvl0, bvh1, bvl1;

    auto load_regs = [&](int kc) {
        avh0 = *(const uint2*)(g_Ah + aOff0 + kc);
        avl0 = *(const uint2*)(g_Al + aOff0 + kc);
        avh1 = *(const uint2*)(g_Ah + aOff1 + kc);
        avl1 = *(const uint2*)(g_Al + aOff1 + kc);
        bvh0 = *(const uint4*)(WTh + bOff0 + kc);
        bvl0 = *(const uint4*)(WTl + bOff0 + kc);
        bvh1 = *(const uint4*)(WTh + bOff1 + kc);
        bvl1 = *(const uint4*)(WTl + bOff1 + kc);
    };

    load_regs(0);

    const int w    = tid >> 5;
    const int lane = tid & 31;
    const int mw   = (w & 1) * 32;
    const int nwp  = (w >> 1) * 32;

    float acc[2][4][4];
    for (int mi = 0; mi < 2; mi++) {
        for (int nj = 0; nj < 4; nj++) {
            for (int q = 0; q < 4; q++) { acc[mi][nj][q] = 0.f; }
        }
    }

    const int aRow = lane & 15;
    const int aK   = (lane >> 4) * 8;
    const int bRow = ((lane >> 4) << 3) + (lane & 7);
    const int bK   = ((lane >> 3) & 1) * 8;
    const unsigned baseAh = smem_u32(sAh);
    const unsigned baseAl = smem_u32(sAl);
    const unsigned baseBh = smem_u32(sBh);
    const unsigned baseBl = smem_u32(sBl);

    for (int chunk = 0; chunk < 8; chunk++) {
        // store staged registers into smem
        *(uint2*)&sAh[rA0 * GP + cA] = avh0;
        *(uint2*)&sAl[rA0 * GP + cA] = avl0;
        *(uint2*)&sAh[rA1 * GP + cA] = avh1;
        *(uint2*)&sAl[rA1 * GP + cA] = avl1;
        *(uint4*)&sBh[nB0 * GP + k8] = bvh0;
        *(uint4*)&sBl[nB0 * GP + k8] = bvl0;
        *(uint4*)&sBh[nB1 * GP + k8] = bvh1;
        *(uint4*)&sBl[nB1 * GP + k8] = bvl1;
        __syncthreads();

        // issue next chunk's global loads (latency hidden behind compute)
        if (chunk < 7) { load_regs((chunk + 1) * 32); }

        #pragma unroll
        for (int ks = 0; ks < 32; ks += 16) {
            unsigned ah[2][4];
            unsigned al[2][4];
            #pragma unroll
            for (int mi = 0; mi < 2; mi++) {
                unsigned off = (unsigned)(((mw + mi * 16 + aRow) * GP + ks + aK) * 2);
                ldm4(ah[mi], baseAh + off);
                ldm4(al[mi], baseAl + off);
            }
            #pragma unroll
            for (int ni = 0; ni < 2; ni++) {
                unsigned bh[4];
                unsigned bl[4];
                unsigned off = (unsigned)(((nwp + ni * 16 + bRow) * GP + ks + bK) * 2);
                ldm4(bh, baseBh + off);
                ldm4(bl, baseBl + off);
                #pragma unroll
                for (int mi = 0; mi < 2; mi++) {
                    mma16816(acc[mi][ni * 2],     ah[mi], bh);
                    mma16816(acc[mi][ni * 2 + 1], ah[mi], bh + 2);
                    mma16816(acc[mi][ni * 2],     ah[mi], bl);
                    mma16816(acc[mi][ni * 2 + 1], ah[mi], bl + 2);
                    mma16816(acc[mi][ni * 2],     al[mi], bh);
                    mma16816(acc[mi][ni * 2 + 1], al[mi], bh + 2);
                }
            }
        }
        __syncthreads();
    }

    #pragma unroll
    for (int mi = 0; mi < 2; mi++) {
        int r0 = mw + mi * 16 + (lane >> 2);
        int ra = sRow[r0];
        int rb = sRow[r0 + 8];
        #pragma unroll
        for (int nj = 0; nj < 4; nj++) {
            int c = col0 + nwp + nj * 8 + (lane & 3) * 2;
            if (ra >= 0) {
                float2 v0;
                v0.x = acc[mi][nj][0];
                v0.y = acc[mi][nj][1];
                *(float2*)(outp + ra + c) = v0;
            }
            if (rb >= 0) {
                float2 v1;
                v1.x = acc[mi][nj][2];
                v1.y = acc[mi][nj][3];
                *(float2*)(outp + rb + c) = v1;
            }
        }
    }
}

// ---------------------------------------------------------------------------
// Kernel 3: attention. One block per query, 256 threads. Warp w == head w.
// Logit phase: 4 keys per warp concurrently, 8 lanes per key (float4 dims,
// self-contained RoPE pairs, 3-shuffle reduce).
// ---------------------------------------------------------------------------
__global__ __launch_bounds__(256) void attn_kernel(const float* __restrict__ rf)
{
    const int n = blockIdx.x;
    const int t = threadIdx.x;

    __shared__ float  F[48];
    __shared__ int    rowOff[KPQ];
    __shared__ float  ksp0[KPQ];
    __shared__ float  ksp1[KPQ];
    __shared__ float  klvl[KPQ];
    __shared__ float2 csn[KPQ * NPAIRS];
    __shared__ float  logits[NHEADS * KPQ];

    if (t < 48) { F[t] = rf[t]; }
    if (t < KPQ) {
        rowOff[t] = g_rowOff[n * KPQ + t];
        ksp0[t]   = g_ksp0[n * KPQ + t];
        ksp1[t]   = g_ksp1[n * KPQ + t];
        int l;
        if      (t < 9)  { l = 0; }
        else if (t < 34) { l = 1; }
        else if (t < 83) { l = 2; }
        else             { l = 3; }
        klvl[t] = (float)l;
    }
    __syncthreads();

    for (int idx = t; idx < KPQ * NPAIRS; idx += 256) {
        int k = idx >> 4;
        int p = idx & 15;
        float ang = ksp0[k] * F[p] + ksp1[k] * F[NPAIRS + p] + klvl[k] * F[2 * NPAIRS + p];
        float sn, cs;
        __sincosf(ang, &sn, &cs);
        csn[idx] = make_float2(cs, sn);
    }
    __syncthreads();

    const int h    = t >> 5;
    const int lane = t & 31;
    const int grp  = lane >> 3;   // 0..3: which key in the 4-key group
    const int sub  = lane & 7;    // 0..7: dim quad within the head

    const float4 q4 = *(const float4*)(g_qrot + n * EMBED + h * HDIM + sub * 4);

    for (int kb = 0; kb < KPQ; kb += 4) {
        int k  = kb + grp;
        int ro = rowOff[k];
        float c = 0.f;
        if (ro >= 0) {
            float4 kv = *(const float4*)(g_Kmap + ro + h * HDIM + sub * 4);
            float2 cs0 = csn[k * NPAIRS + sub * 2];
            float2 cs1 = csn[k * NPAIRS + sub * 2 + 1];
            float r0 = kv.x * cs0.x - kv.y * cs0.y;
            float r1 = kv.x * cs0.y + kv.y * cs0.x;
            float r2 = kv.z * cs1.x - kv.w * cs1.y;
            float r3 = kv.z * cs1.y + kv.w * cs1.x;
            c = q4.x * r0 + q4.y * r1 + q4.z * r2 + q4.w * r3;
        }
        c += __shfl_xor_sync(~0u, c, 1);
        c += __shfl_xor_sync(~0u, c, 2);
        c += __shfl_xor_sync(~0u, c, 4);
        if (sub == 0) {
            logits[h * KPQ + k] = (ro >= 0) ? c * 0.17677669529663687f : -1e9f;
        }
    }
    __syncwarp();

    float m = -1e30f;
    for (int k = lane; k < KPQ; k += 32) { m = fmaxf(m, logits[h * KPQ + k]); }
    for (int o = 16; o; o >>= 1) { m = fmaxf(m, __shfl_xor_sync(~0u, m, o)); }
    float ssum = 0.f;
    for (int k = lane; k < KPQ; k += 32) {
        float e = __expf(logits[h * KPQ + k] - m);
        logits[h * KPQ + k] = e;
        ssum += e;
    }
    for (int o = 16; o; o >>= 1) { ssum += __shfl_xor_sync(~0u, ssum, o); }
    __syncwarp();
    const float inv = 1.0f / ssum;

    float acc = 0.f;
    for (int k = 0; k < KPQ; k++) {
        int ro = rowOff[k];
        if (ro >= 0) { acc += logits[h * KPQ + k] * g_Vmap[ro + t]; }
    }
    g_tmp[n * EMBED + t] = acc * inv;
}

// ---------------------------------------------------------------------------
// Kernel 4: output projection + residual.  4 queries per block.
// ---------------------------------------------------------------------------
__global__ __launch_bounds__(256) void out_proj_kernel(
    const float* __restrict__ query, const float* __restrict__ ow,
    float* __restrict__ out, int n_q)
{
    const int t  = threadIdx.x;
    const int n0 = blockIdx.x * QR;
    __shared__ float xs[QR][EMBED];

    for (int r = 0; r < QR; r++) {
        int n = n0 + r;
        xs[r][t] = (n < n_q) ? g_tmp[n * EMBED + t] : 0.f;
    }
    __syncthreads();

    float acc[QR];
    for (int r = 0; r < QR; r++) { acc[r] = 0.f; }
    #pragma unroll 8
    for (int i = 0; i < EMBED; i++) {
        float w = ow[i * EMBED + t];
        for (int r = 0; r < QR; r++) { acc[r] += xs[r][i] * w; }
    }
    for (int r = 0; r < QR; r++) {
        int n = n0 + r;
        if (n < n_q) { out[n * EMBED + t] = acc[r] + query[n * EMBED + t]; }
    }
}

// ---------------------------------------------------------------------------
extern "C" void kernel_launch(void* const* d_in, const int* in_sizes, int n_in,
                              void* d_out, int out_size)
{
    const float* query = (const float*)d_in[0];
    const float* qpos  = (const float*)d_in[1];
    const float* fm    = (const float*)d_in[2];
    const float* nw    = (const float*)d_in[3];
    const float* nb    = (const float*)d_in[4];
    const float* qw    = (const float*)d_in[5];
    const float* kw    = (const float*)d_in[6];
    const float* vw    = (const float*)d_in[7];
    const float* ow    = (const float*)d_in[8];
    const float* rf    = (const float*)d_in[9];
    const int*   boff  = (const int*)d_in[10];
    const int*   shp   = (const int*)d_in[11];

    int n_q   = in_sizes[0] / EMBED;
    int n_off = in_sizes[10];
    float* out = (float*)d_out;

    int qblocks = (n_q + QR - 1) / QR;
    zero_kernel<<<(NCELLS + 255) / 256, 256>>>();
    prep_kernel<<<n_q, 192>>>(qpos, boff, n_off, shp, n_q);
    compact_kernel<<<(NCELLS + 255) / 256, 256>>>();
    convert_w_kernel<<<(2 * EMBED * EMBED + 255) / 256, 256>>>(kw, vw);
    convert_a_kernel<<<(MAXROWS * 64 + 255) / 256, 256>>>(fm);
    qln_kernel<<<qblocks, 256>>>(query, qpos, nw, nb, qw, rf, n_q);
    kv_gemm_mma<<<dim3(4, (MAXROWS + 63) / 64), 256>>>();
    attn_kernel<<<n_q, 256>>>(rf);
    out_proj_kernel<<<qblocks, 256>>>(query, ow, out, n_q);
}

// round 17
// speedup vs baseline: 1.0447x; 1.0447x over previous
#include <cuda_runtime.h>
#include <cuda_bf16.h>
#include <cuda_fp16.h>
#include <cstdint>
#include <math.h>

#define EMBED   256
#define NHEADS  8
#define HDIM    32
#define NPAIRS  16
#define NLEV    4
#define FULL    128
#define KPQ     164
#define MAXQ    2048
#define MAXB    2
#define NCELLS  (MAXB * NLEV * FULL * FULL)
#define MAXROWS 43520
#define GP      40
#define QR      4

// Scratch (device globals; no runtime allocation allowed). 16B-aligned so
// vector accesses are safe. K/V maps in fp16: halves attn read traffic and
// makes the active footprint (~45 MB) fully L2-resident.
__device__ __align__(16) __half g_Kmap[NCELLS * EMBED];
__device__ __align__(16) __half g_Vmap[NCELLS * EMBED];
__device__ __align__(16) float g_qrot[MAXQ * EMBED];
__device__ __align__(16) float g_tmp [MAXQ * EMBED];
__device__ int   g_mask[NCELLS];
__device__ int   g_rows[NCELLS];
__device__ int   g_nactive;
__device__ int   g_rowOff[MAXQ * KPQ];
__device__ float g_ksp0[MAXQ * KPQ];
__device__ float g_ksp1[MAXQ * KPQ];
__device__ __align__(16) __nv_bfloat16 g_Ah[MAXROWS * EMBED];
__device__ __align__(16) __nv_bfloat16 g_Al[MAXROWS * EMBED];
__device__ __align__(16) __nv_bfloat16 g_WTh[2 * EMBED * EMBED];
__device__ __align__(16) __nv_bfloat16 g_WTl[2 * EMBED * EMBED];

// ---------------------------------------------------------------------------
// mma helpers
// ---------------------------------------------------------------------------
__device__ __forceinline__ unsigned smem_u32(const void* p)
{
    return (unsigned)__cvta_generic_to_shared(p);
}

__device__ __forceinline__ void ldm4(unsigned* r, unsigned a)
{
    asm volatile("ldmatrix.sync.aligned.m8n8.x4.shared.b16 {%0,%1,%2,%3}, [%4];"
        : "=r"(r[0]), "=r"(r[1]), "=r"(r[2]), "=r"(r[3]) : "r"(a));
}

__device__ __forceinline__ void mma16816(float* d, const unsigned* a, const unsigned* b)
{
    asm volatile("mma.sync.aligned.m16n8k16.row.col.f32.bf16.bf16.f32 "
        "{%0,%1,%2,%3}, {%4,%5,%6,%7}, {%8,%9}, {%0,%1,%2,%3};"
        : "+f"(d[0]), "+f"(d[1]), "+f"(d[2]), "+f"(d[3])
        : "r"(a[0]), "r"(a[1]), "r"(a[2]), "r"(a[3]), "r"(b[0]), "r"(b[1]));
}

// ---------------------------------------------------------------------------
__global__ void zero_kernel()
{
    int i = blockIdx.x * blockDim.x + threadIdx.x;
    if (i < NCELLS) { g_mask[i] = 0; }
    if (i == 0) { g_nactive = 0; }
}

// ---------------------------------------------------------------------------
__global__ void prep_kernel(const float* __restrict__ qpos,
                            const int* __restrict__ boff, int n_off,
                            const int* __restrict__ shp, int n_q)
{
    int n = blockIdx.x, t = threadIdx.x;
    if (n >= n_q || t >= KPQ) { return; }
    int l, base;
    if      (t < 9)  { l = 0; base = 0;  }
    else if (t < 34) { l = 1; base = 9;  }
    else if (t < 83) { l = 2; base = 34; }
    else             { l = 3; base = 83; }
    int s = 2 * l + 3, half = l + 1, j = t - base;
    int o0 = j / s - half, o1 = j % s - half;
    int H = shp[2 * l], W = shp[2 * l + 1];
    int maxH = 0, maxW = 0;
    for (int li = 0; li < NLEV; li++) {
        maxH = max(maxH, shp[2 * li]);
        maxW = max(maxW, shp[2 * li + 1]);
    }
    float p0 = qpos[n * 2 + 0], p1 = qpos[n * 2 + 1];
    int c0 = (int)floorf(p0 * ((float)H / (float)maxH));
    int c1 = (int)floorf(p1 * ((float)W / (float)maxW));
    int i0 = c0 + o0, i1 = c1 + o1;
    bool valid = (i0 >= 0) && (i0 < H) && (i1 >= 0) && (i1 < W);
    int b = 0;
    for (int ii = 1; ii < n_off - 1; ii++) {
        if (n >= boff[ii]) { b = ii; }
    }
    int cell = ((b * NLEV + l) * FULL + i0) * FULL + i1;
    g_rowOff[n * KPQ + t] = valid ? cell * EMBED : -1;
    if (valid) { g_mask[cell] = 1; }
    g_ksp0[n * KPQ + t] = (i0 + 0.5f) * ((float)maxH / (float)H);
    g_ksp1[n * KPQ + t] = (i1 + 0.5f) * ((float)maxW / (float)W);
}

// ---------------------------------------------------------------------------
__global__ void compact_kernel()
{
    int i = blockIdx.x * blockDim.x + threadIdx.x;
    if (i < NCELLS && g_mask[i]) {
        int p = atomicAdd(&g_nactive, 1);
        g_rows[p] = i;
    }
}

// ---------------------------------------------------------------------------
__global__ void convert_w_kernel(const float* __restrict__ kw,
                                 const float* __restrict__ vw)
{
    int idx = blockIdx.x * blockDim.x + threadIdx.x;
    if (idx >= 2 * EMBED * EMBED) { return; }
    int w = idx >> 16;
    int rem = idx & 0xFFFF;
    int k = rem >> 8;
    int n = rem & 255;
    float x = (w ? vw : kw)[k * EMBED + n];
    __nv_bfloat16 h = __float2bfloat16(x);
    __nv_bfloat16 lo = __float2bfloat16(x - __bfloat162float(h));
    g_WTh[(w << 16) + n * EMBED + k] = h;
    g_WTl[(w << 16) + n * EMBED + k] = lo;
}

// ---------------------------------------------------------------------------
__global__ __launch_bounds__(256) void convert_a_kernel(const float* __restrict__ fm)
{
    const int nact = g_nactive;
    int e4 = blockIdx.x * blockDim.x + threadIdx.x;
    int r = e4 >> 6;
    if (r >= nact) { return; }
    int c = (e4 & 63) * 4;
    const float4 v = *(const float4*)(fm + g_rows[r] * EMBED + c);
    float xs[4];
    xs[0] = v.x; xs[1] = v.y; xs[2] = v.z; xs[3] = v.w;
    __nv_bfloat16 hh[4];
    __nv_bfloat16 ll[4];
    for (int j = 0; j < 4; j++) {
        hh[j] = __float2bfloat16(xs[j]);
        ll[j] = __float2bfloat16(xs[j] - __bfloat162float(hh[j]));
    }
    *(uint2*)(g_Ah + r * EMBED + c) = *(uint2*)hh;
    *(uint2*)(g_Al + r * EMBED + c) = *(uint2*)ll;
}

// ---------------------------------------------------------------------------
// Kernel 1: LayerNorm + Q projection + RoPE.  4 queries per block.
// ---------------------------------------------------------------------------
__global__ __launch_bounds__(256) void qln_kernel(
    const float* __restrict__ query, const float* __restrict__ qpos,
    const float* __restrict__ nw, const float* __restrict__ nb,
    const float* __restrict__ qw, const float* __restrict__ rf, int n_q)
{
    const int t  = threadIdx.x;
    const int n0 = blockIdx.x * QR;
    __shared__ float xs[QR][EMBED];
    __shared__ float red[16];

    float val[QR];
    for (int r = 0; r < QR; r++) {
        int n = n0 + r;
        val[r] = (n < n_q) ? query[n * EMBED + t] : 0.f;
    }
    for (int r = 0; r < QR; r++) {
        float s = val[r], s2 = val[r] * val[r];
        for (int o = 16; o; o >>= 1) {
            s  += __shfl_xor_sync(~0u, s, o);
            s2 += __shfl_xor_sync(~0u, s2, o);
        }
        int w = t >> 5;
        if ((t & 31) == 0) { red[w] = s; red[8 + w] = s2; }
        __syncthreads();
        float sum = 0.f, sum2 = 0.f;
        for (int i = 0; i < 8; i++) { sum += red[i]; sum2 += red[8 + i]; }
        __syncthreads();
        float mean = sum * (1.0f / EMBED);
        float var  = sum2 * (1.0f / EMBED) - mean * mean;
        float inv  = rsqrtf(var + 1e-5f);
        xs[r][t] = (val[r] - mean) * inv * nw[t] + nb[t];
    }
    __syncthreads();

    float acc[QR];
    for (int r = 0; r < QR; r++) { acc[r] = 0.f; }
    #pragma unroll 8
    for (int i = 0; i < EMBED; i++) {
        float w = qw[i * EMBED + t];
        for (int r = 0; r < QR; r++) { acc[r] += xs[r][i] * w; }
    }
    __syncthreads();
    for (int r = 0; r < QR; r++) { xs[r][t] = acc[r]; }
    __syncthreads();

    const int p = (t & 31) >> 1;
    const float f0 = rf[p], f1 = rf[NPAIRS + p];
    for (int r = 0; r < QR; r++) {
        int n = n0 + r;
        if (n >= n_q) { break; }
        float ang = qpos[n * 2 + 0] * f0 + qpos[n * 2 + 1] * f1;
        float sn, cs;
        __sincosf(ang, &sn, &cs);
        float x1 = xs[r][t & ~1], x2 = xs[r][t | 1];
        g_qrot[n * EMBED + t] = ((t & 1) == 0) ? (x1 * cs - x2 * sn)
                                               : (x1 * sn + x2 * cs);
    }
}

// ---------------------------------------------------------------------------
// Kernel 2: tensor-core K/V GEMM over compacted rows (split bf16, 3 terms).
// R14 known-good loop (synchronous loads, 2 blocks/SM). fp16 epilogue.
// Block: 64 rows x 128 cols. 8 warps as 2(m) x 4(n), warp tile 32x32.
// grid.x: bit1 = K/V weight, bit0 = col half. grid.y: row tiles.
// ---------------------------------------------------------------------------
__global__ __launch_bounds__(256) void kv_gemm_mma()
{
    const int nact = g_nactive;
    const int row0 = blockIdx.y * 64;
    if (row0 >= nact) { return; }

    const int bx   = blockIdx.x;
    const int wsel = (bx >> 1) & 1;
    __half* outp   = wsel ? g_Vmap : g_Kmap;
    const int col0 = (bx & 1) * 128;

    __shared__ __nv_bfloat16 sAh[64 * GP];
    __shared__ __nv_bfloat16 sAl[64 * GP];
    __shared__ __nv_bfloat16 sBh[128 * GP];
    __shared__ __nv_bfloat16 sBl[128 * GP];
    __shared__ int sRow[64];

    const int tid = threadIdx.x;
    if (tid < 64) {
        int r = row0 + tid;
        sRow[tid] = (r < nact) ? g_rows[r] * EMBED : -1;
    }

    const int w    = tid >> 5;
    const int lane = tid & 31;
    const int mw   = (w & 1) * 32;
    const int nwp  = (w >> 1) * 32;

    float acc[2][4][4];
    for (int mi = 0; mi < 2; mi++) {
        for (int nj = 0; nj < 4; nj++) {
            for (int q = 0; q < 4; q++) { acc[mi][nj][q] = 0.f; }
        }
    }

    const int aRow = lane & 15;
    const int aK   = (lane >> 4) * 8;
    const int bRow = ((lane >> 4) << 3) + (lane & 7);
    const int bK   = ((lane >> 3) & 1) * 8;
    const unsigned baseAh = smem_u32(sAh);
    const unsigned baseAl = smem_u32(sAl);
    const unsigned baseBh = smem_u32(sBh);
    const unsigned baseBl = smem_u32(sBl);

    const __nv_bfloat16* WTh = g_WTh + (wsel << 16);
    const __nv_bfloat16* WTl = g_WTl + (wsel << 16);

    for (int kc = 0; kc < EMBED; kc += 32) {
        #pragma unroll
        for (int i = 0; i < 2; i++) {
            int g4 = i * 256 + tid;
            int r  = g4 >> 3;
            int c4 = (g4 & 7) * 4;
            uint2 vh = make_uint2(0u, 0u);
            uint2 vl = make_uint2(0u, 0u);
            if (row0 + r < nact) {
                vh = *(const uint2*)(g_Ah + (row0 + r) * EMBED + kc + c4);
                vl = *(const uint2*)(g_Al + (row0 + r) * EMBED + kc + c4);
            }
            *(uint2*)&sAh[r * GP + c4] = vh;
            *(uint2*)&sAl[r * GP + c4] = vl;
        }
        #pragma unroll
        for (int i = 0; i < 2; i++) {
            int u4 = i * 256 + tid;
            int n  = u4 >> 2;
            int k8 = (u4 & 3) * 8;
            *(uint4*)&sBh[n * GP + k8] = *(const uint4*)(WTh + (col0 + n) * EMBED + kc + k8);
            *(uint4*)&sBl[n * GP + k8] = *(const uint4*)(WTl + (col0 + n) * EMBED + kc + k8);
        }
        __syncthreads();

        #pragma unroll
        for (int ks = 0; ks < 32; ks += 16) {
            unsigned ah[2][4];
            unsigned al[2][4];
            #pragma unroll
            for (int mi = 0; mi < 2; mi++) {
                unsigned off = (unsigned)(((mw + mi * 16 + aRow) * GP + ks + aK) * 2);
                ldm4(ah[mi], baseAh + off);
                ldm4(al[mi], baseAl + off);
            }
            #pragma unroll
            for (int ni = 0; ni < 2; ni++) {
                unsigned bh[4];
                unsigned bl[4];
                unsigned off = (unsigned)(((nwp + ni * 16 + bRow) * GP + ks + bK) * 2);
                ldm4(bh, baseBh + off);
                ldm4(bl, baseBl + off);
                #pragma unroll
                for (int mi = 0; mi < 2; mi++) {
                    mma16816(acc[mi][ni * 2],     ah[mi], bh);
                    mma16816(acc[mi][ni * 2 + 1], ah[mi], bh + 2);
                    mma16816(acc[mi][ni * 2],     ah[mi], bl);
                    mma16816(acc[mi][ni * 2 + 1], ah[mi], bl + 2);
                    mma16816(acc[mi][ni * 2],     al[mi], bh);
                    mma16816(acc[mi][ni * 2 + 1], al[mi], bh + 2);
                }
            }
        }
        __syncthreads();
    }

    // Epilogue: fp16 scatter to padded map layout
    #pragma unroll
    for (int mi = 0; mi < 2; mi++) {
        int r0 = mw + mi * 16 + (lane >> 2);
        int ra = sRow[r0];
        int rb = sRow[r0 + 8];
        #pragma unroll
        for (int nj = 0; nj < 4; nj++) {
            int c = col0 + nwp + nj * 8 + (lane & 3) * 2;
            if (ra >= 0) {
                *(__half2*)(outp + ra + c) =
                    __floats2half2_rn(acc[mi][nj][0], acc[mi][nj][1]);
            }
            if (rb >= 0) {
                *(__half2*)(outp + rb + c) =
                    __floats2half2_rn(acc[mi][nj][2], acc[mi][nj][3]);
            }
        }
    }
}

// ---------------------------------------------------------------------------
// Kernel 3: attention. One block per query, 256 threads. Warp w == head w.
// Logit phase: 4 keys per warp concurrently, 8 lanes per key (fp16x4 loads,
// self-contained RoPE pairs, 3-shuffle reduce). fp16 K/V maps.
// ---------------------------------------------------------------------------
__global__ __launch_bounds__(256) void attn_kernel(const float* __restrict__ rf)
{
    const int n = blockIdx.x;
    const int t = threadIdx.x;

    __shared__ float  F[48];
    __shared__ int    rowOff[KPQ];
    __shared__ float  ksp0[KPQ];
    __shared__ float  ksp1[KPQ];
    __shared__ float  klvl[KPQ];
    __shared__ float2 csn[KPQ * NPAIRS];
    __shared__ float  logits[NHEADS * KPQ];

    if (t < 48) { F[t] = rf[t]; }
    if (t < KPQ) {
        rowOff[t] = g_rowOff[n * KPQ + t];
        ksp0[t]   = g_ksp0[n * KPQ + t];
        ksp1[t]   = g_ksp1[n * KPQ + t];
        int l;
        if      (t < 9)  { l = 0; }
        else if (t < 34) { l = 1; }
        else if (t < 83) { l = 2; }
        else             { l = 3; }
        klvl[t] = (float)l;
    }
    __syncthreads();

    for (int idx = t; idx < KPQ * NPAIRS; idx += 256) {
        int k = idx >> 4;
        int p = idx & 15;
        float ang = ksp0[k] * F[p] + ksp1[k] * F[NPAIRS + p] + klvl[k] * F[2 * NPAIRS + p];
        float sn, cs;
        __sincosf(ang, &sn, &cs);
        csn[idx] = make_float2(cs, sn);
    }
    __syncthreads();

    const int h    = t >> 5;
    const int lane = t & 31;
    const int grp  = lane >> 3;   // 0..3: which key in the 4-key group
    const int sub  = lane & 7;    // 0..7: dim quad within the head

    const float4 q4 = *(const float4*)(g_qrot + n * EMBED + h * HDIM + sub * 4);

    for (int kb = 0; kb < KPQ; kb += 4) {
        int k  = kb + grp;
        int ro = rowOff[k];
        float c = 0.f;
        if (ro >= 0) {
            uint2 raw = *(const uint2*)(g_Kmap + ro + h * HDIM + sub * 4);
            float2 k01 = __half22float2(*(__half2*)&raw.x);
            float2 k23 = __half22float2(*(__half2*)&raw.y);
            float2 cs0 = csn[k * NPAIRS + sub * 2];
            float2 cs1 = csn[k * NPAIRS + sub * 2 + 1];
            float r0 = k01.x * cs0.x - k01.y * cs0.y;
            float r1 = k01.x * cs0.y + k01.y * cs0.x;
            float r2 = k23.x * cs1.x - k23.y * cs1.y;
            float r3 = k23.x * cs1.y + k23.y * cs1.x;
            c = q4.x * r0 + q4.y * r1 + q4.z * r2 + q4.w * r3;
        }
        c += __shfl_xor_sync(~0u, c, 1);
        c += __shfl_xor_sync(~0u, c, 2);
        c += __shfl_xor_sync(~0u, c, 4);
        if (sub == 0) {
            logits[h * KPQ + k] = (ro >= 0) ? c * 0.17677669529663687f : -1e9f;
        }
    }
    __syncwarp();

    float m = -1e30f;
    for (int k = lane; k < KPQ; k += 32) { m = fmaxf(m, logits[h * KPQ + k]); }
    for (int o = 16; o; o >>= 1) { m = fmaxf(m, __shfl_xor_sync(~0u, m, o)); }
    float ssum = 0.f;
    for (int k = lane; k < KPQ; k += 32) {
        float e = __expf(logits[h * KPQ + k] - m);
        logits[h * KPQ + k] = e;
        ssum += e;
    }
    for (int o = 16; o; o >>= 1) { ssum += __shfl_xor_sync(~0u, ssum, o); }
    __syncwarp();
    const float inv = 1.0f / ssum;

    float acc = 0.f;
    for (int k = 0; k < KPQ; k++) {
        int ro = rowOff[k];
        if (ro >= 0) { acc += logits[h * KPQ + k] * __half2float(g_Vmap[ro + t]); }
    }
    g_tmp[n * EMBED + t] = acc * inv;
}

// ---------------------------------------------------------------------------
// Kernel 4: output projection + residual.  4 queries per block.
// ---------------------------------------------------------------------------
__global__ __launch_bounds__(256) void out_proj_kernel(
    const float* __restrict__ query, const float* __restrict__ ow,
    float* __restrict__ out, int n_q)
{
    const int t  = threadIdx.x;
    const int n0 = blockIdx.x * QR;
    __shared__ float xs[QR][EMBED];

    for (int r = 0; r < QR; r++) {
        int n = n0 + r;
        xs[r][t] = (n < n_q) ? g_tmp[n * EMBED + t] : 0.f;
    }
    __syncthreads();

    float acc[QR];
    for (int r = 0; r < QR; r++) { acc[r] = 0.f; }
    #pragma unroll 8
    for (int i = 0; i < EMBED; i++) {
        float w = ow[i * EMBED + t];
        for (int r = 0; r < QR; r++) { acc[r] += xs[r][i] * w; }
    }
    for (int r = 0; r < QR; r++) {
        int n = n0 + r;
        if (n < n_q) { out[n * EMBED + t] = acc[r] + query[n * EMBED + t]; }
    }
}

// ---------------------------------------------------------------------------
extern "C" void kernel_launch(void* const* d_in, const int* in_sizes, int n_in,
                              void* d_out, int out_size)
{
    const float* query = (const float*)d_in[0];
    const float* qpos  = (const float*)d_in[1];
    const float* fm    = (const float*)d_in[2];
    const float* nw    = (const float*)d_in[3];
    const float* nb    = (const float*)d_in[4];
    const float* qw    = (const float*)d_in[5];
    const float* kw    = (const float*)d_in[6];
    const float* vw    = (const float*)d_in[7];
    const float* ow    = (const float*)d_in[8];
    const float* rf    = (const float*)d_in[9];
    const int*   boff  = (const int*)d_in[10];
    const int*   shp   = (const int*)d_in[11];

    int n_q   = in_sizes[0] / EMBED;
    int n_off = in_sizes[10];
    float* out = (float*)d_out;

    int qblocks = (n_q + QR - 1) / QR;
    zero_kernel<<<(NCELLS + 255) / 256, 256>>>();
    prep_kernel<<<n_q, 192>>>(qpos, boff, n_off, shp, n_q);
    compact_kernel<<<(NCELLS + 255) / 256, 256>>>();
    convert_w_kernel<<<(2 * EMBED * EMBED + 255) / 256, 256>>>(kw, vw);
    convert_a_kernel<<<(MAXROWS * 64 + 255) / 256, 256>>>(fm);
    qln_kernel<<<qblocks, 256>>>(query, qpos, nw, nb, qw, rf, n_q);
    kv_gemm_mma<<<dim3(4, (MAXROWS + 63) / 64), 256>>>();
    attn_kernel<<<n_q, 256>>>(rf);
    out_proj_kernel<<<qblocks, 256>>>(query, ow, out, n_q);
}